// round 15
// baseline (speedup 1.0000x reference)
#include <cuda_runtime.h>
#include <stdint.h>

// Problem constants (from reference)
#define MASS_H2O   18.01056f
#define MASS_NH3   17.02655f
#define MAX_MZ     30000
#define WINDOW     10
#define VOCAB      26
#define BATCH      32768
#define IONS       8

#define TOTAL_GROUPS     (BATCH * VOCAB)               // 851,968
#define TILE_GROUPS      256
#define NUM_TILES        (TOTAL_GROUPS / TILE_GROUPS)  // 3328 exactly
#define WINDOWS_PER_TILE (TILE_GROUPS * IONS)          // 2048
#define ELEMS_PER_TILE   (WINDOWS_PER_TILE * WINDOW)   // 20480
#define VEC2_PER_TILE    (ELEMS_PER_TILE / 2)          // 10240
#define THREADS          1024
#define VEC2_PER_THREAD  (VEC2_PER_TILE / THREADS)     // 10
#define ABATCH           5                             // per-batch MLP depth

#define METABUF     (WINDOWS_PER_TILE + 4)             // +pad
#define BAD_IDX     (-(1 << 30))                       // masked-window sentinel
#define GRID_BLOCKS 304                                // 2 CTAs per SM

// One ion-variant window base from c (already cb or cy). EXACT reference
// arithmetic: variant first (single rounding), then *10, round-half-even.
__device__ __forceinline__
int one_meta(float c, int jj, bool vok)
{
    float m;
    if      (jj == 1) m = c - MASS_H2O;
    else if (jj == 2) m = c - MASS_NH3;
    else if (jj == 3) m = c * 0.5f;
    else              m = c;
    const int  idx  = __float2int_rn(m * 10.0f) - (WINDOW / 2);
    const bool keep = (idx >= 0) && (idx <= MAX_MZ - WINDOW) && vok;
    return keep ? idx : BAD_IDX;
}

__global__ void __launch_bounds__(THREADS, 2)
intensity_kernel(const float* __restrict__ pepmass,
                 const float* __restrict__ prefix_mass,
                 const float* __restrict__ masses,
                 const float* __restrict__ spectrum,
                 const int*   __restrict__ dir_ptr,
                 float* __restrict__ out)
{
    // Only metadata lives in SMEM (16.4 KB static) -> 2 CTAs/SM, and the
    // 120 KB spectrum stays resident in the ~195 KB L1D as read-only data.
    __shared__ int meta[2][METABUF];

    const int tid  = threadIdx.x;
    const int dir  = dir_ptr ? __ldg(dir_ptr) : 0;
    // Thread owns windows {2*tid, 2*tid+1}: group gl = tid/4, ion pair
    // (2*(tid&3), 2*(tid&3)+1).  The pair never straddles the cb/cy split.
    const int gl   = tid >> 2;
    const int ion0 = (tid & 3) * 2;

    // ---- prologue: prefetch tile-0 inputs (L2-only: protect L1 spectrum) --
    float pm, pf, ms;
    int   v;
    {
        const int g = blockIdx.x * TILE_GROUPS + gl;
        const int b = g / VOCAB;  v = g - b * VOCAB;
        pm = __ldcg(pepmass + b); pf = __ldcg(prefix_mass + b);
        ms = __ldcg(masses + v);
    }

    int parity = 0;
    for (int tile = blockIdx.x; tile < NUM_TILES; tile += GRID_BLOCKS) {
        int* mb = meta[parity];
        parity ^= 1;

        // ---- publish this tile's metadata: 2 windows, one STS.64 ----
        {
            float cb, cy;
            if (dir == 0) { cb = pf + ms; cy = pm - cb; }
            else          { cy = pf + ms; cb = pm - cy; }
            const float c   = (ion0 < 4) ? cb : cy;
            const bool  vok = (v >= 3);
            int2 mw;
            mw.x = one_meta(c, ion0 & 3, vok);
            mw.y = one_meta(c, (ion0 + 1) & 3, vok);
            reinterpret_cast<int2*>(mb)[tid] = mw;   // windows 2tid, 2tid+1
        }

        // ---- issue NEXT tile's loads BEFORE the barrier (latency drains
        //      during the convoy; consumers only at next loop top) ----
        {
            int nt = tile + GRID_BLOCKS;
            if (nt >= NUM_TILES) nt = tile;          // clamp: harmless reload
            const int g = nt * TILE_GROUPS + gl;
            const int b = g / VOCAB;  v = g - b * VOCAB;
            pm = __ldcg(pepmass + b); pf = __ldcg(prefix_mass + b);
            ms = __ldcg(masses + v);
        }

        __syncthreads();

        // ---------- Phase 2: 10 float2 per thread, L1-cached gathers -------
        // A float2 at even element offset NEVER straddles a window.
        float2* out2 = reinterpret_cast<float2*>(out) + tile * VEC2_PER_TILE;

        #pragma unroll
        for (int kk = 0; kk < VEC2_PER_THREAD / ABATCH; ++kk) {
            const int q0 = tid + kk * ABATCH * THREADS;
            int addr[ABATCH];

            #pragma unroll
            for (int j = 0; j < ABATCH; ++j) {
                const int q = q0 + j * THREADS;
                const unsigned win = (unsigned)q / 5u;   // window = (2q)/10
                const int w0 = (q - (int)win * 5) * 2;   // in {0,2,4,6,8}
                addr[j] = mb[win] + w0;                  // LDS.32 meta burst
            }

            float2 val[ABATCH];
            #pragma unroll
            for (int j = 0; j < ABATCH; ++j) {
                const bool ok = (addr[j] >= 0);          // sentinel -> masked
                val[j].x = ok ? __ldg(spectrum + addr[j])     : 0.0f;
                val[j].y = ok ? __ldg(spectrum + addr[j] + 1) : 0.0f;
            }

            #pragma unroll
            for (int j = 0; j < ABATCH; ++j)
                __stcs(out2 + q0 + j * THREADS, val[j]); // streaming STG.64
        }
        // no trailing sync: double-buffered metadata (the barrier above
        // proves all readers of the other buffer finished before rewrite)
    }
}

extern "C" void kernel_launch(void* const* d_in, const int* in_sizes, int n_in,
                              void* d_out, int out_size)
{
    const float* spectrum    = (const float*)d_in[0];
    const float* pepmass     = (const float*)d_in[1];
    const float* prefix_mass = (const float*)d_in[2];
    const float* masses      = (const float*)d_in[3];
    const int*   dir_ptr     = (n_in >= 5) ? (const int*)d_in[4] : nullptr;
    float*       out         = (float*)d_out;

    intensity_kernel<<<GRID_BLOCKS, THREADS>>>(
        pepmass, prefix_mass, masses, spectrum, dir_ptr, out);
}

// round 16
// speedup vs baseline: 1.4606x; 1.4606x over previous
#include <cuda_runtime.h>
#include <stdint.h>

// Problem constants (from reference)
#define MASS_H2O   18.01056f
#define MASS_NH3   17.02655f
#define MAX_MZ     30000
#define WINDOW     10
#define VOCAB      26
#define BATCH      32768
#define IONS       8

#define TOTAL_GROUPS     (BATCH * VOCAB)               // 851,968
#define TILE_GROUPS      512
#define NUM_TILES        (TOTAL_GROUPS / TILE_GROUPS)  // 1664 exactly
#define WINDOWS_PER_TILE (TILE_GROUPS * IONS)          // 4096
#define ELEMS_PER_TILE   (WINDOWS_PER_TILE * WINDOW)   // 40960
#define VEC2_PER_TILE    (ELEMS_PER_TILE / 2)          // 20480
#define THREADS          1024
#define VEC2_PER_THREAD  (VEC2_PER_TILE / THREADS)     // 20
#define ABATCH           5                             // batch width
#define NBATCH           (VEC2_PER_THREAD / ABATCH)    // 4 batches

#define SPEC_FLOATS_PAD  30016                  // 30000 + 16 zero pad
#define SPEC_BYTES       (SPEC_FLOATS_PAD * 4)  // 120,064
#define METABUF          (WINDOWS_PER_TILE + 4)
#define META_BYTES       (2 * METABUF * 4)      // double buffer: 32,800
#define SMEM_BYTES       (SPEC_BYTES + META_BYTES)     // 152,864

#define ZERO_IDX    30000                       // points at zero pad
#define GRID_BLOCKS 152

// One ion-variant window base from c (already cb or cy). EXACT reference
// arithmetic: variant first (single rounding), then *10, round-half-even.
__device__ __forceinline__
int one_meta(float c, int jj, bool vok)
{
    float m;
    if      (jj == 1) m = c - MASS_H2O;
    else if (jj == 2) m = c - MASS_NH3;
    else if (jj == 3) m = c * 0.5f;
    else              m = c;
    const int  idx  = __float2int_rn(m * 10.0f) - (WINDOW / 2);
    const bool keep = (idx >= 0) && (idx <= MAX_MZ - WINDOW) && vok;
    return keep ? idx : ZERO_IDX;
}

// Meta-address burst for batch kk: 5 independent LDS.32.
__device__ __forceinline__
void meta_burst(const int* __restrict__ mb, int tid, int kk, int addr[ABATCH])
{
    #pragma unroll
    for (int j = 0; j < ABATCH; ++j) {
        const int q = tid + (kk * ABATCH + j) * THREADS;
        const unsigned win = (unsigned)q / 5u;       // window = (2q)/10
        const int w0 = (q - (int)win * 5) * 2;       // in {0,2,4,6,8}
        addr[j] = mb[win] + w0;
    }
}

__global__ void __launch_bounds__(THREADS, 1)
intensity_kernel(const float* __restrict__ pepmass,
                 const float* __restrict__ prefix_mass,
                 const float* __restrict__ masses,
                 const float* __restrict__ spectrum,
                 const int*   __restrict__ dir_ptr,
                 float* __restrict__ out)
{
    extern __shared__ unsigned char smem_raw[];
    float* spec = reinterpret_cast<float*>(smem_raw);
    int*   meta = reinterpret_cast<int*>(smem_raw + SPEC_BYTES);

    const int tid  = threadIdx.x;
    const int dir  = dir_ptr ? __ldg(dir_ptr) : 0;
    const int gl   = tid >> 1;          // group within tile owned by thread
    const int half = tid & 1;           // 0 -> ions 0..3 (cb), 1 -> ions 4..7 (cy)

    // ---- stage spectrum into SMEM (zero the 16-float pad) ----
    {
        const float4* s4 = reinterpret_cast<const float4*>(spectrum);
        float4*       d4 = reinterpret_cast<float4*>(spec);
        const float4  z4 = make_float4(0.f, 0.f, 0.f, 0.f);
        #pragma unroll 2
        for (int i = tid; i < SPEC_FLOATS_PAD / 4; i += THREADS)
            d4[i] = (i < MAX_MZ / 4) ? s4[i] : z4;
    }

    // ---- prologue: prefetch tile-0 inputs (3 LDGs per thread) ----
    float pm, pf, ms;
    int   v;
    {
        const int g = blockIdx.x * TILE_GROUPS + gl;
        const int b = g / VOCAB;  v = g - b * VOCAB;
        pm = __ldg(pepmass + b); pf = __ldg(prefix_mass + b); ms = __ldg(masses + v);
    }

    int parity = 0;
    for (int tile = blockIdx.x; tile < NUM_TILES; tile += GRID_BLOCKS) {
        int* mb = meta + parity * METABUF;
        parity ^= 1;

        // ---- publish this tile's metadata: 4 windows, one STS.128 ----
        {
            float cb, cy;
            if (dir == 0) { cb = pf + ms; cy = pm - cb; }
            else          { cy = pf + ms; cb = pm - cy; }
            const float c   = half ? cy : cb;
            const bool  vok = (v >= 3);
            int4 mw;
            mw.x = one_meta(c, 0, vok);
            mw.y = one_meta(c, 1, vok);
            mw.z = one_meta(c, 2, vok);
            mw.w = one_meta(c, 3, vok);
            reinterpret_cast<int4*>(mb)[tid] = mw;   // windows 4*tid..4*tid+3
        }

        // ---- issue NEXT tile's 3 loads BEFORE the barrier: latency drains
        //      during the convoy; consumers only at the next loop top ----
        {
            int nt = tile + GRID_BLOCKS;
            if (nt >= NUM_TILES) nt = tile;          // clamp: harmless reload
            const int g = nt * TILE_GROUPS + gl;
            const int b = g / VOCAB;  v = g - b * VOCAB;
            pm = __ldg(pepmass + b); pf = __ldg(prefix_mass + b); ms = __ldg(masses + v);
        }

        __syncthreads();   // (first iteration: also covers spectrum staging)

        // ---------- Phase 2: register-rotated meta pipeline ----------
        // Batch kk's meta addresses were loaded DURING batch kk-1's
        // gathers/stores, so the 29-cyc meta LDS latency is never exposed.
        float2* out2 = reinterpret_cast<float2*>(out) + tile * VEC2_PER_TILE;

        int addrA[ABATCH];
        meta_burst(mb, tid, 0, addrA);               // prologue burst

        #pragma unroll
        for (int kk = 0; kk < NBATCH; ++kk) {
            int addrB[ABATCH];
            if (kk + 1 < NBATCH)
                meta_burst(mb, tid, kk + 1, addrB);  // hide under gathers

            float2 val[ABATCH];
            #pragma unroll
            for (int j = 0; j < ABATCH; ++j) {
                val[j].x = spec[addrA[j]];
                val[j].y = spec[addrA[j] + 1];
            }

            const int q0 = tid + kk * ABATCH * THREADS;
            #pragma unroll
            for (int j = 0; j < ABATCH; ++j)
                __stcs(out2 + q0 + j * THREADS, val[j]);   // streaming STG.64

            #pragma unroll
            for (int j = 0; j < ABATCH; ++j)
                addrA[j] = addrB[j];                 // rotate (dead on last)
        }
        // no trailing sync: double-buffered metadata (the barrier above
        // proves all readers of the other buffer finished before rewrite)
    }
}

extern "C" void kernel_launch(void* const* d_in, const int* in_sizes, int n_in,
                              void* d_out, int out_size)
{
    const float* spectrum    = (const float*)d_in[0];
    const float* pepmass     = (const float*)d_in[1];
    const float* prefix_mass = (const float*)d_in[2];
    const float* masses      = (const float*)d_in[3];
    const int*   dir_ptr     = (n_in >= 5) ? (const int*)d_in[4] : nullptr;
    float*       out         = (float*)d_out;

    cudaFuncSetAttribute(intensity_kernel,
                         cudaFuncAttributeMaxDynamicSharedMemorySize, SMEM_BYTES);

    intensity_kernel<<<GRID_BLOCKS, THREADS, SMEM_BYTES>>>(
        pepmass, prefix_mass, masses, spectrum, dir_ptr, out);
}